// round 1
// baseline (speedup 1.0000x reference)
#include <cuda_runtime.h>
#include <cuda_bf16.h>
#include <math.h>

// Problem dims (fixed by the dataset)
#define BATCH   4
#define SEQ     2048
#define NTOK    (BATCH*SEQ)      // 8192
#define DIM     1024
#define HID     2048             // hidden; up produces 2*HID
#define NEXP    8

typedef unsigned long long ull;

// -------- scratch (no allocation allowed -> device globals) --------
__device__ float g_xn[(size_t)NTOK * DIM];      // 32 MB  normalized x
__device__ float g_u [(size_t)NTOK * HID];      // 64 MB  swiglu output
__device__ int   g_tokmap[NEXP * NTOK];
__device__ int   g_count[NEXP];

// -------- packed f32x2 helpers (sm_103a) --------
__device__ __forceinline__ ull pack2(float lo, float hi) {
    ull r; asm("mov.b64 %0, {%1, %2};" : "=l"(r) : "f"(lo), "f"(hi)); return r;
}
__device__ __forceinline__ void unpack2(ull v, float& lo, float& hi) {
    asm("mov.b64 {%0, %1}, %2;" : "=f"(lo), "=f"(hi) : "l"(v));
}
__device__ __forceinline__ ull ffma2(ull a, ull b, ull c) {
    ull d; asm("fma.rn.f32x2 %0, %1, %2, %3;" : "=l"(d) : "l"(a), "l"(b), "l"(c)); return d;
}

// ====================================================================
// Kernel 0: zero expert counters
// ====================================================================
__global__ void zero_counts_kernel() {
    if (threadIdx.x < NEXP) g_count[threadIdx.x] = 0;
}

// ====================================================================
// Kernel 1: RMSNorm + nearest-centroid routing. One block per token.
// 256 threads, each handles 4 contiguous floats (float4).
// ====================================================================
__global__ __launch_bounds__(256)
void route_kernel(const float* __restrict__ x,
                  const float* __restrict__ scale,
                  const float* __restrict__ cent) {
    const int t   = blockIdx.x;
    const int tid = threadIdx.x;
    const int lane = tid & 31, wid = tid >> 5;

    const float4 xv = ((const float4*)(x + (size_t)t * DIM))[tid];

    // sum of squares -> mean
    float ss = xv.x*xv.x + xv.y*xv.y + xv.z*xv.z + xv.w*xv.w;
    #pragma unroll
    for (int o = 16; o; o >>= 1) ss += __shfl_xor_sync(0xFFFFFFFFu, ss, o);
    __shared__ float swarp[8];
    if (lane == 0) swarp[wid] = ss;
    __syncthreads();
    float mean = 0.f;
    #pragma unroll
    for (int w = 0; w < 8; w++) mean += swarp[w];
    mean *= (1.0f / DIM);
    const float inv = rsqrtf(mean + 1e-6f);

    const float4 sc = ((const float4*)scale)[tid];
    float4 v;
    v.x = xv.x * (sc.x * inv);
    v.y = xv.y * (sc.y * inv);
    v.z = xv.z * (sc.z * inv);
    v.w = xv.w * (sc.w * inv);
    ((float4*)(g_xn + (size_t)t * DIM))[tid] = v;

    // per-expert partial of (|c|^2 - 2 xn.c)  (the |xn|^2 term is expert-independent)
    float p[NEXP];
    #pragma unroll
    for (int e = 0; e < NEXP; e++) {
        const float4 c = ((const float4*)(cent + (size_t)e * DIM))[tid];
        p[e] = (c.x*c.x - 2.f*v.x*c.x) + (c.y*c.y - 2.f*v.y*c.y)
             + (c.z*c.z - 2.f*v.z*c.z) + (c.w*c.w - 2.f*v.w*c.w);
    }
    __shared__ float sred[NEXP][8];
    #pragma unroll
    for (int e = 0; e < NEXP; e++) {
        float s = p[e];
        #pragma unroll
        for (int o = 16; o; o >>= 1) s += __shfl_xor_sync(0xFFFFFFFFu, s, o);
        if (lane == 0) sred[e][wid] = s;
    }
    __syncthreads();
    if (tid == 0) {
        int best = 0; float bd = 3.4e38f;
        #pragma unroll
        for (int e = 0; e < NEXP; e++) {
            float d = 0.f;
            #pragma unroll
            for (int w = 0; w < 8; w++) d += sred[e][w];
            if (d < bd) { bd = d; best = e; }
        }
        int pos = atomicAdd(&g_count[best], 1);
        g_tokmap[best * NTOK + pos] = t;
    }
}

// ====================================================================
// Kernel 2: up GEMM + SwiGLU (gathered per expert).
// Tile: 128 tokens x (64 a-cols + 64 g-cols). 256 threads, 8x8/thread
// per half using packed f32x2 FMAs. grid = (64 m-tiles, 32 n-tiles, 8 exp)
// ====================================================================
#define BM 128
#define BK 16

__global__ __launch_bounds__(256)
void up_kernel(const float* __restrict__ up_w) {
    const int e   = blockIdx.z;
    const int cnt = g_count[e];
    const int m0  = blockIdx.x * BM;
    if (m0 >= cnt) return;
    const int n0  = blockIdx.y * 64;

    __shared__ float Xs[BK][BM + 4];
    __shared__ float Ws[BK][128];
    __shared__ int   rows[BM];

    const int tid = threadIdx.x;
    if (tid < BM) {
        int i = m0 + tid;
        rows[tid] = g_tokmap[e * NTOK + (i < cnt ? i : cnt - 1)];
    }
    __syncthreads();

    const int tx = tid & 15, ty = tid >> 4;
    ull acc_a[8][2]; ull acc_g[8][2];
    #pragma unroll
    for (int r = 0; r < 8; r++) {
        acc_a[r][0] = acc_a[r][1] = 0ull;
        acc_g[r][0] = acc_g[r][1] = 0ull;
    }

    const float* W = up_w + (size_t)e * DIM * (2 * HID);

    for (int k0 = 0; k0 < DIM; k0 += BK) {
        // X tile: 128 rows x 16 k (gathered)
        #pragma unroll
        for (int i = 0; i < 2; i++) {
            int idx = tid + i * 256;
            int r = idx >> 2, kq = idx & 3;
            float4 v = *(const float4*)(g_xn + (size_t)rows[r] * DIM + k0 + kq * 4);
            Xs[kq*4+0][r] = v.x; Xs[kq*4+1][r] = v.y;
            Xs[kq*4+2][r] = v.z; Xs[kq*4+3][r] = v.w;
        }
        // W tile: 16 k x (64 a-cols | 64 g-cols)
        #pragma unroll
        for (int i = 0; i < 2; i++) {
            int idx = tid + i * 256;
            int kk = idx >> 5, c4 = idx & 31;
            int n  = (c4 < 16) ? (n0 + c4 * 4) : (n0 + HID + (c4 - 16) * 4);
            float4 v = *(const float4*)(W + (size_t)(k0 + kk) * (2 * HID) + n);
            *(float4*)&Ws[kk][c4 * 4] = v;
        }
        __syncthreads();

        #pragma unroll
        for (int kk = 0; kk < BK; kk++) {
            ull wa0 = *(const ull*)&Ws[kk][tx * 4];
            ull wa1 = *(const ull*)&Ws[kk][tx * 4 + 2];
            ull wg0 = *(const ull*)&Ws[kk][64 + tx * 4];
            ull wg1 = *(const ull*)&Ws[kk][64 + tx * 4 + 2];
            float4 xq0 = *(const float4*)&Xs[kk][ty * 8];
            float4 xq1 = *(const float4*)&Xs[kk][ty * 8 + 4];
            float xv[8] = {xq0.x,xq0.y,xq0.z,xq0.w, xq1.x,xq1.y,xq1.z,xq1.w};
            #pragma unroll
            for (int r = 0; r < 8; r++) {
                ull xx = pack2(xv[r], xv[r]);
                acc_a[r][0] = ffma2(xx, wa0, acc_a[r][0]);
                acc_a[r][1] = ffma2(xx, wa1, acc_a[r][1]);
                acc_g[r][0] = ffma2(xx, wg0, acc_g[r][0]);
                acc_g[r][1] = ffma2(xx, wg1, acc_g[r][1]);
            }
        }
        __syncthreads();
    }

    #pragma unroll
    for (int r = 0; r < 8; r++) {
        int i = m0 + ty * 8 + r;
        if (i < cnt) {
            int token = rows[ty * 8 + r];
            float a0,a1,a2,a3, b0,b1,b2,b3;
            unpack2(acc_a[r][0], a0, a1);
            unpack2(acc_a[r][1], a2, a3);
            unpack2(acc_g[r][0], b0, b1);
            unpack2(acc_g[r][1], b2, b3);
            float4 o;
            o.x = a0 * b0 / (1.f + expf(-b0));
            o.y = a1 * b1 / (1.f + expf(-b1));
            o.z = a2 * b2 / (1.f + expf(-b2));
            o.w = a3 * b3 / (1.f + expf(-b3));
            *(float4*)(g_u + (size_t)token * HID + n0 + tx * 4) = o;
        }
    }
}

// ====================================================================
// Kernel 3: down GEMM + skip add + scatter to output.
// Tile: 128 tokens x 128 out-cols. grid = (64, 8, 8 experts)
// ====================================================================
__global__ __launch_bounds__(256)
void down_kernel(const float* __restrict__ down_w,
                 const float* __restrict__ x,
                 float* __restrict__ out) {
    const int e   = blockIdx.z;
    const int cnt = g_count[e];
    const int m0  = blockIdx.x * BM;
    if (m0 >= cnt) return;
    const int n0  = blockIdx.y * 128;

    __shared__ float Xs[BK][BM + 4];
    __shared__ float Ws[BK][128];
    __shared__ int   rows[BM];

    const int tid = threadIdx.x;
    if (tid < BM) {
        int i = m0 + tid;
        rows[tid] = g_tokmap[e * NTOK + (i < cnt ? i : cnt - 1)];
    }
    __syncthreads();

    const int tx = tid & 15, ty = tid >> 4;
    ull acc[8][4];
    #pragma unroll
    for (int r = 0; r < 8; r++)
        #pragma unroll
        for (int j = 0; j < 4; j++) acc[r][j] = 0ull;

    const float* W = down_w + (size_t)e * HID * DIM;

    for (int k0 = 0; k0 < HID; k0 += BK) {
        #pragma unroll
        for (int i = 0; i < 2; i++) {
            int idx = tid + i * 256;
            int r = idx >> 2, kq = idx & 3;
            float4 v = *(const float4*)(g_u + (size_t)rows[r] * HID + k0 + kq * 4);
            Xs[kq*4+0][r] = v.x; Xs[kq*4+1][r] = v.y;
            Xs[kq*4+2][r] = v.z; Xs[kq*4+3][r] = v.w;
        }
        #pragma unroll
        for (int i = 0; i < 2; i++) {
            int idx = tid + i * 256;
            int kk = idx >> 5, c4 = idx & 31;
            int n  = n0 + c4 * 4;
            float4 v = *(const float4*)(W + (size_t)(k0 + kk) * DIM + n);
            *(float4*)&Ws[kk][c4 * 4] = v;
        }
        __syncthreads();

        #pragma unroll
        for (int kk = 0; kk < BK; kk++) {
            ull w0 = *(const ull*)&Ws[kk][tx * 8];
            ull w1 = *(const ull*)&Ws[kk][tx * 8 + 2];
            ull w2 = *(const ull*)&Ws[kk][tx * 8 + 4];
            ull w3 = *(const ull*)&Ws[kk][tx * 8 + 6];
            float4 xq0 = *(const float4*)&Xs[kk][ty * 8];
            float4 xq1 = *(const float4*)&Xs[kk][ty * 8 + 4];
            float xv[8] = {xq0.x,xq0.y,xq0.z,xq0.w, xq1.x,xq1.y,xq1.z,xq1.w};
            #pragma unroll
            for (int r = 0; r < 8; r++) {
                ull xx = pack2(xv[r], xv[r]);
                acc[r][0] = ffma2(xx, w0, acc[r][0]);
                acc[r][1] = ffma2(xx, w1, acc[r][1]);
                acc[r][2] = ffma2(xx, w2, acc[r][2]);
                acc[r][3] = ffma2(xx, w3, acc[r][3]);
            }
        }
        __syncthreads();
    }

    #pragma unroll
    for (int r = 0; r < 8; r++) {
        int i = m0 + ty * 8 + r;
        if (i < cnt) {
            int token = rows[ty * 8 + r];
            float z0,z1,z2,z3,z4,z5,z6,z7;
            unpack2(acc[r][0], z0, z1);
            unpack2(acc[r][1], z2, z3);
            unpack2(acc[r][2], z4, z5);
            unpack2(acc[r][3], z6, z7);
            const float* xs = x + (size_t)token * DIM + n0 + tx * 8;
            float4 s0 = ((const float4*)xs)[0];
            float4 s1 = ((const float4*)xs)[1];
            float4 o0, o1;
            o0.x = z0 + s0.x; o0.y = z1 + s0.y; o0.z = z2 + s0.z; o0.w = z3 + s0.w;
            o1.x = z4 + s1.x; o1.y = z5 + s1.y; o1.z = z6 + s1.z; o1.w = z7 + s1.w;
            float* op = out + (size_t)token * DIM + n0 + tx * 8;
            ((float4*)op)[0] = o0;
            ((float4*)op)[1] = o1;
        }
    }
}

// ====================================================================
extern "C" void kernel_launch(void* const* d_in, const int* in_sizes, int n_in,
                              void* d_out, int out_size) {
    const float* x      = (const float*)d_in[0];   // [4,2048,1024]
    const float* scale  = (const float*)d_in[1];   // [1024]
    const float* cent   = (const float*)d_in[2];   // [8,1024]
    const float* up_w   = (const float*)d_in[3];   // [8,1024,4096]
    const float* down_w = (const float*)d_in[4];   // [8,2048,1024]
    float* out = (float*)d_out;                    // [4,2048,1024]

    zero_counts_kernel<<<1, 32>>>();
    route_kernel<<<NTOK, 256>>>(x, scale, cent);
    up_kernel<<<dim3(NTOK / BM, HID / 64, NEXP), 256>>>(up_w);
    down_kernel<<<dim3(NTOK / BM, DIM / 128, NEXP), 256>>>(down_w, x, out);
}

// round 3
// speedup vs baseline: 2.1241x; 2.1241x over previous
#include <cuda_runtime.h>
#include <cuda_bf16.h>
#include <math.h>
#include <stdint.h>

#define NTOK    8192
#define DIM     1024
#define HID     2048
#define NEXP    8

// ---------------- scratch (device globals; no allocation allowed) ----------
__device__ __nv_bfloat16 g_xh[(size_t)NTOK * DIM];           // x_norm hi
__device__ __nv_bfloat16 g_xl[(size_t)NTOK * DIM];           // x_norm lo
__device__ __nv_bfloat16 g_uwh[(size_t)NEXP * 4096 * 1024];  // up W^T hi, n' interleaved (a,g)
__device__ __nv_bfloat16 g_uwl[(size_t)NEXP * 4096 * 1024];  // up W^T lo
__device__ __nv_bfloat16 g_dwh[(size_t)NEXP * 1024 * 2048];  // down W^T hi [e][n][k]
__device__ __nv_bfloat16 g_dwl[(size_t)NEXP * 1024 * 2048];  // down W^T lo
__device__ __nv_bfloat16 g_uh[(size_t)NTOK * HID];           // swiglu hi
__device__ __nv_bfloat16 g_ul[(size_t)NTOK * HID];           // swiglu lo
__device__ int g_tokmap[NEXP * NTOK];
__device__ int g_count[NEXP];

// ---------------- helpers ----------------------------------------------
__device__ __forceinline__ uint32_t smem_u32(const void* p) {
    uint32_t a;
    asm("{ .reg .u64 t; cvta.to.shared.u64 t, %1; cvt.u32.u64 %0, t; }" : "=r"(a) : "l"(p));
    return a;
}
__device__ __forceinline__ void cp16(uint32_t dst, const void* src) {
    asm volatile("cp.async.cg.shared.global [%0], [%1], 16;" :: "r"(dst), "l"(src));
}
#define CP_COMMIT() asm volatile("cp.async.commit_group;")
#define SWZ128(o) ((o) ^ (((o) >> 3) & 0x70))

__device__ __forceinline__ void ldsm4(uint32_t* r, uint32_t addr) {
    asm volatile("ldmatrix.sync.aligned.m8n8.x4.shared.b16 {%0,%1,%2,%3}, [%4];"
        : "=r"(r[0]), "=r"(r[1]), "=r"(r[2]), "=r"(r[3]) : "r"(addr));
}
__device__ __forceinline__ void mma16816(float* c, const uint32_t* a, uint32_t b0, uint32_t b1) {
    asm volatile("mma.sync.aligned.m16n8k16.row.col.f32.bf16.bf16.f32 "
        "{%0,%1,%2,%3}, {%4,%5,%6,%7}, {%8,%9}, {%0,%1,%2,%3};"
        : "+f"(c[0]), "+f"(c[1]), "+f"(c[2]), "+f"(c[3])
        : "r"(a[0]), "r"(a[1]), "r"(a[2]), "r"(a[3]), "r"(b0), "r"(b1));
}
__device__ __forceinline__ uint32_t pack_bf(__nv_bfloat16 a, __nv_bfloat16 b) {
    return (uint32_t)__bfloat16_as_ushort(a) | ((uint32_t)__bfloat16_as_ushort(b) << 16);
}

// ---------------- smem layout for MMA kernels ------------------------------
#define OFF_AH   0
#define OFF_AL   16384
#define OFF_BH   32768
#define OFF_BL   49152
#define STAGE_SZ 65536
#define SM_TILES 1024
#define SMEM_MMA (1024 + 3*STAGE_SZ)   // 197632 B

// ====================================================================
// Kernel 0: zero expert counters
// ====================================================================
__global__ void zero_counts_kernel() {
    if (threadIdx.x < NEXP) g_count[threadIdx.x] = 0;
}

// ====================================================================
// Kernel 1: RMSNorm + routing; writes x_norm as bf16 hi/lo
// ====================================================================
__global__ __launch_bounds__(256)
void route_kernel(const float* __restrict__ x,
                  const float* __restrict__ scale,
                  const float* __restrict__ cent) {
    const int t = blockIdx.x, tid = threadIdx.x;
    const int lane = tid & 31, wid = tid >> 5;

    const float4 xv = ((const float4*)(x + (size_t)t * DIM))[tid];
    float ss = xv.x*xv.x + xv.y*xv.y + xv.z*xv.z + xv.w*xv.w;
    #pragma unroll
    for (int o = 16; o; o >>= 1) ss += __shfl_xor_sync(0xFFFFFFFFu, ss, o);
    __shared__ float swarp[8];
    if (lane == 0) swarp[wid] = ss;
    __syncthreads();
    float mean = 0.f;
    #pragma unroll
    for (int w = 0; w < 8; w++) mean += swarp[w];
    const float inv = rsqrtf(mean * (1.0f / DIM) + 1e-6f);

    const float4 sc = ((const float4*)scale)[tid];
    float v[4];
    v[0] = xv.x * (sc.x * inv); v[1] = xv.y * (sc.y * inv);
    v[2] = xv.z * (sc.z * inv); v[3] = xv.w * (sc.w * inv);

    uint32_t ph[2], pl[2];
    #pragma unroll
    for (int q = 0; q < 2; q++) {
        __nv_bfloat16 h0 = __float2bfloat16(v[2*q]);
        __nv_bfloat16 h1 = __float2bfloat16(v[2*q+1]);
        __nv_bfloat16 l0 = __float2bfloat16(v[2*q]   - __bfloat162float(h0));
        __nv_bfloat16 l1 = __float2bfloat16(v[2*q+1] - __bfloat162float(h1));
        ph[q] = pack_bf(h0, h1); pl[q] = pack_bf(l0, l1);
    }
    ((uint2*)(g_xh + (size_t)t * DIM))[tid] = make_uint2(ph[0], ph[1]);
    ((uint2*)(g_xl + (size_t)t * DIM))[tid] = make_uint2(pl[0], pl[1]);

    float p[NEXP];
    #pragma unroll
    for (int e = 0; e < NEXP; e++) {
        const float4 c = ((const float4*)(cent + (size_t)e * DIM))[tid];
        p[e] = (c.x*c.x - 2.f*v[0]*c.x) + (c.y*c.y - 2.f*v[1]*c.y)
             + (c.z*c.z - 2.f*v[2]*c.z) + (c.w*c.w - 2.f*v[3]*c.w);
    }
    __shared__ float sred[NEXP][8];
    #pragma unroll
    for (int e = 0; e < NEXP; e++) {
        float s = p[e];
        #pragma unroll
        for (int o = 16; o; o >>= 1) s += __shfl_xor_sync(0xFFFFFFFFu, s, o);
        if (lane == 0) sred[e][wid] = s;
    }
    __syncthreads();
    if (tid == 0) {
        int best = 0; float bd = 3.4e38f;
        #pragma unroll
        for (int e = 0; e < NEXP; e++) {
            float d = 0.f;
            #pragma unroll
            for (int w = 0; w < 8; w++) d += sred[e][w];
            if (d < bd) { bd = d; best = e; }
        }
        int pos = atomicAdd(&g_count[best], 1);
        g_tokmap[best * NTOK + pos] = t;
    }
}

// ====================================================================
// Kernel 2a: up weight convert+transpose, interleaving a/g columns:
//   col<2048 (a_j)  -> n' = 2j ;  col>=2048 (g_j) -> n' = 2j+1
// ====================================================================
__global__ __launch_bounds__(256)
void conv_up_kernel(const float* __restrict__ w) {   // [8][1024][4096]
    __shared__ float tile[32][33];
    const int e = blockIdx.z, n0 = blockIdx.x * 32, k0 = blockIdx.y * 32;
    const int tx = threadIdx.x & 31, ty = threadIdx.x >> 5;
    const float* W = w + ((size_t)e * 1024 + k0) * 4096 + n0;
    #pragma unroll
    for (int j = 0; j < 4; j++)
        tile[ty + 8*j][tx] = W[(size_t)(ty + 8*j) * 4096 + tx];
    __syncthreads();
    #pragma unroll
    for (int j = 0; j < 4; j++) {
        int n = ty + 8*j;
        int col = n0 + n;
        int nprime = (col < 2048) ? (2 * col) : (2 * (col - 2048) + 1);
        float v = tile[tx][n];
        __nv_bfloat16 h = __float2bfloat16(v);
        __nv_bfloat16 l = __float2bfloat16(v - __bfloat162float(h));
        size_t o = ((size_t)e * 4096 + nprime) * 1024 + k0 + tx;
        g_uwh[o] = h; g_uwl[o] = l;
    }
}

__global__ __launch_bounds__(256)
void conv_down_kernel(const float* __restrict__ w) { // [8][2048][1024] -> [e][n][k]
    __shared__ float tile[32][33];
    const int e = blockIdx.z, n0 = blockIdx.x * 32, k0 = blockIdx.y * 32;
    const int tx = threadIdx.x & 31, ty = threadIdx.x >> 5;
    const float* W = w + ((size_t)e * 2048 + k0) * 1024 + n0;
    #pragma unroll
    for (int j = 0; j < 4; j++)
        tile[ty + 8*j][tx] = W[(size_t)(ty + 8*j) * 1024 + tx];
    __syncthreads();
    #pragma unroll
    for (int j = 0; j < 4; j++) {
        int n = ty + 8*j;
        float v = tile[tx][n];
        __nv_bfloat16 h = __float2bfloat16(v);
        __nv_bfloat16 l = __float2bfloat16(v - __bfloat162float(h));
        size_t o = ((size_t)e * 1024 + n0 + n) * 2048 + k0 + tx;
        g_dwh[o] = h; g_dwl[o] = l;
    }
}

// ====================================================================
// Shared mainloop machinery (BM=128, BN=128, BK=64, 8 warps 4x2)
// ====================================================================
__device__ __forceinline__ void load_chunk(uint32_t st, const int* rows_s, int tid,
                                           const __nv_bfloat16* Ah, const __nv_bfloat16* Al,
                                           const __nv_bfloat16* Bh, const __nv_bfloat16* Bl,
                                           int n0, int k0, int kstride) {
    #pragma unroll
    for (int i = 0; i < 4; i++) {
        int idx = tid + i * 256;
        int r = idx >> 3, sg = idx & 7;
        uint32_t off = SWZ128((uint32_t)(r * 128 + sg * 16));
        size_t soA = (size_t)rows_s[r] * kstride + k0 + sg * 8;
        cp16(st + OFF_AH + off, Ah + soA);
        cp16(st + OFF_AL + off, Al + soA);
        size_t soB = (size_t)(n0 + r) * kstride + k0 + sg * 8;
        cp16(st + OFF_BH + off, Bh + soB);
        cp16(st + OFF_BL + off, Bl + soB);
    }
}

__device__ __forceinline__ void compute_chunk(uint32_t st, int lane, int mbase_w, int nbase_w,
                                              float acc[2][8][4]) {
    const int rsel = lane & 15;
    const int csel = lane >> 4;
    #pragma unroll
    for (int k16 = 0; k16 < 4; k16++) {
        const int cg = k16 * 2 + csel;
        uint32_t ah[2][4], al[2][4], bh[4][4], bl[4][4];
        #pragma unroll
        for (int mf = 0; mf < 2; mf++) {
            uint32_t boff = SWZ128((uint32_t)((mbase_w + mf*16 + rsel) * 128 + cg * 16));
            ldsm4(ah[mf], st + OFF_AH + boff);
            ldsm4(al[mf], st + OFF_AL + boff);
        }
        #pragma unroll
        for (int q = 0; q < 4; q++) {
            uint32_t boff = SWZ128((uint32_t)((nbase_w + q*16 + rsel) * 128 + cg * 16));
            ldsm4(bh[q], st + OFF_BH + boff);
            ldsm4(bl[q], st + OFF_BL + boff);
        }
        #pragma unroll
        for (int mf = 0; mf < 2; mf++)
            #pragma unroll
            for (int q = 0; q < 4; q++)
                #pragma unroll
                for (int s = 0; s < 2; s++) {
                    float* c = acc[mf][2*q + s];
                    mma16816(c, ah[mf], bh[q][s], bh[q][2 + s]);   // hh
                    mma16816(c, al[mf], bh[q][s], bh[q][2 + s]);   // lh
                    mma16816(c, ah[mf], bl[q][s], bl[q][2 + s]);   // hl
                }
    }
}

// ====================================================================
// Kernel 3: up GEMM + SwiGLU (n' interleaved a/g -> per-thread swiglu)
// ====================================================================
__global__ __launch_bounds__(256, 1)
void up_mma_kernel() {
    extern __shared__ char smem[];
    int* rows_s = (int*)smem;
    const uint32_t sb = smem_u32(smem);
    const int tid = threadIdx.x, lane = tid & 31, wid = tid >> 5;
    const int e = blockIdx.z;
    const int cnt = g_count[e];
    const int m0 = blockIdx.x * 128;
    if (m0 >= cnt) return;
    const int n0 = blockIdx.y * 128;     // n' base

    if (tid < 128) {
        int i = m0 + tid;
        rows_s[tid] = g_tokmap[e * NTOK + (i < cnt ? i : cnt - 1)];
    }
    __syncthreads();

    const __nv_bfloat16* Bh = g_uwh + (size_t)e * 4096 * 1024;
    const __nv_bfloat16* Bl = g_uwl + (size_t)e * 4096 * 1024;

    const int NC = 16;   // 1024 / 64
    load_chunk(sb + SM_TILES,            rows_s, tid, g_xh, g_xl, Bh, Bl, n0, 0,  DIM); CP_COMMIT();
    load_chunk(sb + SM_TILES + STAGE_SZ, rows_s, tid, g_xh, g_xl, Bh, Bl, n0, 64, DIM); CP_COMMIT();

    float acc[2][8][4];
    #pragma unroll
    for (int a = 0; a < 2; a++)
        #pragma unroll
        for (int b = 0; b < 8; b++)
            #pragma unroll
            for (int c = 0; c < 4; c++) acc[a][b][c] = 0.f;

    const int mbase_w = (wid & 3) * 32, nbase_w = (wid >> 2) * 64;

    #pragma unroll 1
    for (int c = 0; c < NC; c++) {
        if (c < NC - 1) asm volatile("cp.async.wait_group 1;" ::: "memory");
        else            asm volatile("cp.async.wait_group 0;" ::: "memory");
        __syncthreads();
        if (c + 2 < NC) {
            load_chunk(sb + SM_TILES + ((c+2)%3)*STAGE_SZ, rows_s, tid,
                       g_xh, g_xl, Bh, Bl, n0, (c+2)*64, DIM);
            CP_COMMIT();
        }
        compute_chunk(sb + SM_TILES + (c%3)*STAGE_SZ, lane, mbase_w, nbase_w, acc);
    }

    // Epilogue: per-thread SwiGLU on (even n' = a, odd n' = g) pairs
    const int j0 = blockIdx.y * 64;
    #pragma unroll
    for (int mf = 0; mf < 2; mf++) {
        #pragma unroll
        for (int nf = 0; nf < 8; nf++) {
            const float* c = acc[mf][nf];
            int j = j0 + (nbase_w >> 1) + nf * 4 + (lane & 3);
            #pragma unroll
            for (int r2 = 0; r2 < 2; r2++) {
                int mrow = mbase_w + mf*16 + (lane >> 2) + r2*8;
                if (m0 + mrow < cnt) {
                    float a = c[r2*2 + 0], g = c[r2*2 + 1];
                    float y = a * g / (1.f + __expf(-g));
                    __nv_bfloat16 h = __float2bfloat16(y);
                    __nv_bfloat16 l = __float2bfloat16(y - __bfloat162float(h));
                    size_t o = (size_t)rows_s[mrow] * HID + j;
                    g_uh[o] = h; g_ul[o] = l;
                }
            }
        }
    }
}

// ====================================================================
// Kernel 4: down GEMM + skip add + scatter
// ====================================================================
__global__ __launch_bounds__(256, 1)
void down_mma_kernel(const float* __restrict__ x, float* __restrict__ out) {
    extern __shared__ char smem[];
    int* rows_s = (int*)smem;
    const uint32_t sb = smem_u32(smem);
    const int tid = threadIdx.x, lane = tid & 31, wid = tid >> 5;
    const int e = blockIdx.z;
    const int cnt = g_count[e];
    const int m0 = blockIdx.x * 128;
    if (m0 >= cnt) return;
    const int n0 = blockIdx.y * 128;

    if (tid < 128) {
        int i = m0 + tid;
        rows_s[tid] = g_tokmap[e * NTOK + (i < cnt ? i : cnt - 1)];
    }
    __syncthreads();

    const __nv_bfloat16* Bh = g_dwh + (size_t)e * 1024 * 2048;
    const __nv_bfloat16* Bl = g_dwl + (size_t)e * 1024 * 2048;

    const int NC = 32;   // 2048 / 64
    load_chunk(sb + SM_TILES,            rows_s, tid, g_uh, g_ul, Bh, Bl, n0, 0,  HID); CP_COMMIT();
    load_chunk(sb + SM_TILES + STAGE_SZ, rows_s, tid, g_uh, g_ul, Bh, Bl, n0, 64, HID); CP_COMMIT();

    float acc[2][8][4];
    #pragma unroll
    for (int a = 0; a < 2; a++)
        #pragma unroll
        for (int b = 0; b < 8; b++)
            #pragma unroll
            for (int c = 0; c < 4; c++) acc[a][b][c] = 0.f;

    const int mbase_w = (wid & 3) * 32, nbase_w = (wid >> 2) * 64;

    #pragma unroll 1
    for (int c = 0; c < NC; c++) {
        if (c < NC - 1) asm volatile("cp.async.wait_group 1;" ::: "memory");
        else            asm volatile("cp.async.wait_group 0;" ::: "memory");
        __syncthreads();
        if (c + 2 < NC) {
            load_chunk(sb + SM_TILES + ((c+2)%3)*STAGE_SZ, rows_s, tid,
                       g_uh, g_ul, Bh, Bl, n0, (c+2)*64, HID);
            CP_COMMIT();
        }
        compute_chunk(sb + SM_TILES + (c%3)*STAGE_SZ, lane, mbase_w, nbase_w, acc);
    }

    // Epilogue: + skip, scatter fp32
    #pragma unroll
    for (int mf = 0; mf < 2; mf++) {
        #pragma unroll
        for (int nf = 0; nf < 8; nf++) {
            const float* c = acc[mf][nf];
            int n = n0 + nbase_w + nf*8 + (lane & 3)*2;
            #pragma unroll
            for (int r2 = 0; r2 < 2; r2++) {
                int mrow = mbase_w + mf*16 + (lane >> 2) + r2*8;
                if (m0 + mrow < cnt) {
                    int token = rows_s[mrow];
                    float2 s = *(const float2*)(x + (size_t)token * DIM + n);
                    float2 o;
                    o.x = c[r2*2 + 0] + s.x;
                    o.y = c[r2*2 + 1] + s.y;
                    *(float2*)(out + (size_t)token * DIM + n) = o;
                }
            }
        }
    }
}

// ====================================================================
extern "C" void kernel_launch(void* const* d_in, const int* in_sizes, int n_in,
                              void* d_out, int out_size) {
    const float* x      = (const float*)d_in[0];   // [4,2048,1024]
    const float* scale  = (const float*)d_in[1];   // [1024]
    const float* cent   = (const float*)d_in[2];   // [8,1024]
    const float* up_w   = (const float*)d_in[3];   // [8,1024,4096]
    const float* down_w = (const float*)d_in[4];   // [8,2048,1024]
    float* out = (float*)d_out;                    // [4,2048,1024]

    cudaFuncSetAttribute(up_mma_kernel,   cudaFuncAttributeMaxDynamicSharedMemorySize, SMEM_MMA);
    cudaFuncSetAttribute(down_mma_kernel, cudaFuncAttributeMaxDynamicSharedMemorySize, SMEM_MMA);

    zero_counts_kernel<<<1, 32>>>();
    route_kernel<<<NTOK, 256>>>(x, scale, cent);
    conv_up_kernel<<<dim3(128, 32, NEXP), 256>>>(up_w);
    conv_down_kernel<<<dim3(32, 64, NEXP), 256>>>(down_w);
    up_mma_kernel<<<dim3(64, 32, NEXP), 256, SMEM_MMA>>>();
    down_mma_kernel<<<dim3(64, 8, NEXP), 256, SMEM_MMA>>>(x, out);
}

// round 4
// speedup vs baseline: 2.4276x; 1.1429x over previous
#include <cuda_runtime.h>
#include <cuda_bf16.h>
#include <math.h>
#include <stdint.h>

#define NTOK    8192
#define DIM     1024
#define HID     2048
#define NEXP    8

// ---------------- scratch (device globals; no allocation allowed) ----------
__device__ __nv_bfloat16 g_xh[(size_t)NTOK * DIM];           // x_norm hi
__device__ __nv_bfloat16 g_xl[(size_t)NTOK * DIM];           // x_norm lo
__device__ __nv_bfloat16 g_uwh[(size_t)NEXP * 4096 * 1024];  // up W^T hi, n' interleaved (a,g)
__device__ __nv_bfloat16 g_uwl[(size_t)NEXP * 4096 * 1024];  // up W^T lo
__device__ __nv_bfloat16 g_dwh[(size_t)NEXP * 1024 * 2048];  // down W^T hi [e][n][k]
__device__ __nv_bfloat16 g_dwl[(size_t)NEXP * 1024 * 2048];  // down W^T lo
__device__ __nv_bfloat16 g_uh[(size_t)NTOK * HID];           // swiglu hi
__device__ __nv_bfloat16 g_ul[(size_t)NTOK * HID];           // swiglu lo
__device__ int g_tokmap[NEXP * NTOK];
__device__ int g_count[NEXP];

// ---------------- helpers ----------------------------------------------
__device__ __forceinline__ uint32_t smem_u32(const void* p) {
    uint32_t a;
    asm("{ .reg .u64 t; cvta.to.shared.u64 t, %1; cvt.u32.u64 %0, t; }" : "=r"(a) : "l"(p));
    return a;
}
__device__ __forceinline__ void cp16(uint32_t dst, const void* src) {
    asm volatile("cp.async.cg.shared.global [%0], [%1], 16;" :: "r"(dst), "l"(src));
}
#define CP_COMMIT() asm volatile("cp.async.commit_group;")
// SW64 swizzle for 64-byte tile rows
#define SWZ64(o) ((o) ^ (((o) >> 3) & 0x30))

__device__ __forceinline__ void ldsm4(uint32_t* r, uint32_t addr) {
    asm volatile("ldmatrix.sync.aligned.m8n8.x4.shared.b16 {%0,%1,%2,%3}, [%4];"
        : "=r"(r[0]), "=r"(r[1]), "=r"(r[2]), "=r"(r[3]) : "r"(addr));
}
__device__ __forceinline__ void mma16816(float* c, const uint32_t* a, uint32_t b0, uint32_t b1) {
    asm volatile("mma.sync.aligned.m16n8k16.row.col.f32.bf16.bf16.f32 "
        "{%0,%1,%2,%3}, {%4,%5,%6,%7}, {%8,%9}, {%0,%1,%2,%3};"
        : "+f"(c[0]), "+f"(c[1]), "+f"(c[2]), "+f"(c[3])
        : "r"(a[0]), "r"(a[1]), "r"(a[2]), "r"(a[3]), "r"(b0), "r"(b1));
}
__device__ __forceinline__ uint32_t pack_bf(__nv_bfloat16 a, __nv_bfloat16 b) {
    return (uint32_t)__bfloat16_as_ushort(a) | ((uint32_t)__bfloat16_as_ushort(b) << 16);
}

// ---------------- smem layout for MMA kernels (BK=32, 64B rows) ------------
#define OFF_AH   0
#define OFF_AL   8192
#define OFF_BH   16384
#define OFF_BL   24576
#define STAGE_SZ 32768
#define SM_TILES 1024
#define SMEM_MMA (1024 + 3*STAGE_SZ)   // 99328 B -> 2 CTAs/SM

// ====================================================================
__global__ void zero_counts_kernel() {
    if (threadIdx.x < NEXP) g_count[threadIdx.x] = 0;
}

// ====================================================================
// Kernel 1: RMSNorm + routing; writes x_norm as bf16 hi/lo
// ====================================================================
__global__ __launch_bounds__(256)
void route_kernel(const float* __restrict__ x,
                  const float* __restrict__ scale,
                  const float* __restrict__ cent) {
    const int t = blockIdx.x, tid = threadIdx.x;
    const int lane = tid & 31, wid = tid >> 5;

    const float4 xv = ((const float4*)(x + (size_t)t * DIM))[tid];
    float ss = xv.x*xv.x + xv.y*xv.y + xv.z*xv.z + xv.w*xv.w;
    #pragma unroll
    for (int o = 16; o; o >>= 1) ss += __shfl_xor_sync(0xFFFFFFFFu, ss, o);
    __shared__ float swarp[8];
    if (lane == 0) swarp[wid] = ss;
    __syncthreads();
    float mean = 0.f;
    #pragma unroll
    for (int w = 0; w < 8; w++) mean += swarp[w];
    const float inv = rsqrtf(mean * (1.0f / DIM) + 1e-6f);

    const float4 sc = ((const float4*)scale)[tid];
    float v[4];
    v[0] = xv.x * (sc.x * inv); v[1] = xv.y * (sc.y * inv);
    v[2] = xv.z * (sc.z * inv); v[3] = xv.w * (sc.w * inv);

    uint32_t ph[2], pl[2];
    #pragma unroll
    for (int q = 0; q < 2; q++) {
        __nv_bfloat16 h0 = __float2bfloat16(v[2*q]);
        __nv_bfloat16 h1 = __float2bfloat16(v[2*q+1]);
        __nv_bfloat16 l0 = __float2bfloat16(v[2*q]   - __bfloat162float(h0));
        __nv_bfloat16 l1 = __float2bfloat16(v[2*q+1] - __bfloat162float(h1));
        ph[q] = pack_bf(h0, h1); pl[q] = pack_bf(l0, l1);
    }
    ((uint2*)(g_xh + (size_t)t * DIM))[tid] = make_uint2(ph[0], ph[1]);
    ((uint2*)(g_xl + (size_t)t * DIM))[tid] = make_uint2(pl[0], pl[1]);

    float p[NEXP];
    #pragma unroll
    for (int e = 0; e < NEXP; e++) {
        const float4 c = ((const float4*)(cent + (size_t)e * DIM))[tid];
        p[e] = (c.x*c.x - 2.f*v[0]*c.x) + (c.y*c.y - 2.f*v[1]*c.y)
             + (c.z*c.z - 2.f*v[2]*c.z) + (c.w*c.w - 2.f*v[3]*c.w);
    }
    __shared__ float sred[NEXP][8];
    #pragma unroll
    for (int e = 0; e < NEXP; e++) {
        float s = p[e];
        #pragma unroll
        for (int o = 16; o; o >>= 1) s += __shfl_xor_sync(0xFFFFFFFFu, s, o);
        if (lane == 0) sred[e][wid] = s;
    }
    __syncthreads();
    if (tid == 0) {
        int best = 0; float bd = 3.4e38f;
        #pragma unroll
        for (int e = 0; e < NEXP; e++) {
            float d = 0.f;
            #pragma unroll
            for (int w = 0; w < 8; w++) d += sred[e][w];
            if (d < bd) { bd = d; best = e; }
        }
        int pos = atomicAdd(&g_count[best], 1);
        g_tokmap[best * NTOK + pos] = t;
    }
}

// ====================================================================
// Kernel 2a: up weight convert+transpose (a/g interleaved), coalesced 4B writes
// tile: 32 n x 64 k
// ====================================================================
__global__ __launch_bounds__(256)
void conv_up_kernel(const float* __restrict__ w) {   // [8][1024][4096]
    __shared__ float tile[32][65];
    const int e = blockIdx.z, n0 = blockIdx.x * 32, k0 = blockIdx.y * 64;
    const int tid = threadIdx.x;
    const float* W = w + ((size_t)e * 1024 + k0) * 4096 + n0;
    #pragma unroll
    for (int i = 0; i < 8; i++) {
        int idx = tid + i * 256;
        int kk = idx >> 5, nn = idx & 31;
        tile[nn][kk] = W[(size_t)kk * 4096 + nn];
    }
    __syncthreads();
    #pragma unroll
    for (int i = 0; i < 4; i++) {
        int idx = tid + i * 256;
        int nn = idx >> 5, kp = idx & 31;
        float v0 = tile[nn][2*kp], v1 = tile[nn][2*kp+1];
        __nv_bfloat16 h0 = __float2bfloat16(v0), h1 = __float2bfloat16(v1);
        __nv_bfloat16 l0 = __float2bfloat16(v0 - __bfloat162float(h0));
        __nv_bfloat16 l1 = __float2bfloat16(v1 - __bfloat162float(h1));
        int col = n0 + nn;
        int nprime = (col < 2048) ? (2 * col) : (2 * (col - 2048) + 1);
        size_t o32 = ((((size_t)e * 4096 + nprime) * 1024 + k0) >> 1) + kp;
        ((uint32_t*)g_uwh)[o32] = pack_bf(h0, h1);
        ((uint32_t*)g_uwl)[o32] = pack_bf(l0, l1);
    }
}

__global__ __launch_bounds__(256)
void conv_down_kernel(const float* __restrict__ w) { // [8][2048][1024] -> [e][n][k]
    __shared__ float tile[32][65];
    const int e = blockIdx.z, n0 = blockIdx.x * 32, k0 = blockIdx.y * 64;
    const int tid = threadIdx.x;
    const float* W = w + ((size_t)e * 2048 + k0) * 1024 + n0;
    #pragma unroll
    for (int i = 0; i < 8; i++) {
        int idx = tid + i * 256;
        int kk = idx >> 5, nn = idx & 31;
        tile[nn][kk] = W[(size_t)kk * 1024 + nn];
    }
    __syncthreads();
    #pragma unroll
    for (int i = 0; i < 4; i++) {
        int idx = tid + i * 256;
        int nn = idx >> 5, kp = idx & 31;
        float v0 = tile[nn][2*kp], v1 = tile[nn][2*kp+1];
        __nv_bfloat16 h0 = __float2bfloat16(v0), h1 = __float2bfloat16(v1);
        __nv_bfloat16 l0 = __float2bfloat16(v0 - __bfloat162float(h0));
        __nv_bfloat16 l1 = __float2bfloat16(v1 - __bfloat162float(h1));
        size_t o32 = ((((size_t)e * 1024 + n0 + nn) * 2048 + k0) >> 1) + kp;
        ((uint32_t*)g_dwh)[o32] = pack_bf(h0, h1);
        ((uint32_t*)g_dwl)[o32] = pack_bf(l0, l1);
    }
}

// ====================================================================
// Mainloop machinery (BM=128, BN=128, BK=32, 8 warps 4x2, warp tile 32x64)
// ====================================================================
__device__ __forceinline__ void load_chunk(uint32_t st, const int* rows_s, int tid,
                                           const __nv_bfloat16* Ah, const __nv_bfloat16* Al,
                                           const __nv_bfloat16* Bh, const __nv_bfloat16* Bl,
                                           int n0, int k0, int kstride) {
    #pragma unroll
    for (int i = 0; i < 2; i++) {
        int idx = tid + i * 256;
        int r = idx >> 2, sg = idx & 3;
        uint32_t off = SWZ64((uint32_t)(r * 64 + sg * 16));
        size_t soA = (size_t)rows_s[r] * kstride + k0 + sg * 8;
        cp16(st + OFF_AH + off, Ah + soA);
        cp16(st + OFF_AL + off, Al + soA);
        size_t soB = (size_t)(n0 + r) * kstride + k0 + sg * 8;
        cp16(st + OFF_BH + off, Bh + soB);
        cp16(st + OFF_BL + off, Bl + soB);
    }
}

__device__ __forceinline__ void compute_chunk(uint32_t st, int lane, int mbase_w, int nbase_w,
                                              float acc[2][8][4]) {
    const int rsel = lane & 15;
    const int csel = lane >> 4;
    #pragma unroll
    for (int k16 = 0; k16 < 2; k16++) {
        const int cg = k16 * 2 + csel;
        uint32_t ah[2][4], al[2][4];
        #pragma unroll
        for (int mf = 0; mf < 2; mf++) {
            uint32_t boff = SWZ64((uint32_t)((mbase_w + mf*16 + rsel) * 64 + cg * 16));
            ldsm4(ah[mf], st + OFF_AH + boff);
            ldsm4(al[mf], st + OFF_AL + boff);
        }
        #pragma unroll
        for (int q = 0; q < 4; q++) {
            uint32_t bh[4], bl[4];
            uint32_t boff = SWZ64((uint32_t)((nbase_w + q*16 + rsel) * 64 + cg * 16));
            ldsm4(bh, st + OFF_BH + boff);
            ldsm4(bl, st + OFF_BL + boff);
            #pragma unroll
            for (int s = 0; s < 2; s++) {
                #pragma unroll
                for (int mf = 0; mf < 2; mf++) {
                    float* c = acc[mf][2*q + s];
                    mma16816(c, ah[mf], bh[s], bh[2 + s]);   // hh
                    mma16816(c, al[mf], bh[s], bh[2 + s]);   // lh
                    mma16816(c, ah[mf], bl[s], bl[2 + s]);   // hl
                }
            }
        }
    }
}

// ====================================================================
// Kernel 3: up GEMM + SwiGLU (n' interleaved a/g), smem-staged epilogue
// ====================================================================
__global__ __launch_bounds__(256, 2)
void up_mma_kernel() {
    extern __shared__ char smem[];
    int* rows_s = (int*)smem;
    const uint32_t sb = smem_u32(smem);
    const int tid = threadIdx.x, lane = tid & 31, wid = tid >> 5;
    const int e = blockIdx.z;
    const int cnt = g_count[e];
    const int m0 = blockIdx.x * 128;
    if (m0 >= cnt) return;
    const int n0 = blockIdx.y * 128;     // n' base

    if (tid < 128) {
        int i = m0 + tid;
        rows_s[tid] = g_tokmap[e * NTOK + (i < cnt ? i : cnt - 1)];
    }
    __syncthreads();

    const __nv_bfloat16* Bh = g_uwh + (size_t)e * 4096 * 1024;
    const __nv_bfloat16* Bl = g_uwl + (size_t)e * 4096 * 1024;

    const int NC = 32;   // 1024 / 32
    load_chunk(sb + SM_TILES,            rows_s, tid, g_xh, g_xl, Bh, Bl, n0, 0,  DIM); CP_COMMIT();
    load_chunk(sb + SM_TILES + STAGE_SZ, rows_s, tid, g_xh, g_xl, Bh, Bl, n0, 32, DIM); CP_COMMIT();

    float acc[2][8][4];
    #pragma unroll
    for (int a = 0; a < 2; a++)
        #pragma unroll
        for (int b = 0; b < 8; b++)
            #pragma unroll
            for (int c = 0; c < 4; c++) acc[a][b][c] = 0.f;

    const int mbase_w = (wid & 3) * 32, nbase_w = (wid >> 2) * 64;

    #pragma unroll 1
    for (int c = 0; c < NC; c++) {
        if (c < NC - 1) asm volatile("cp.async.wait_group 1;" ::: "memory");
        else            asm volatile("cp.async.wait_group 0;" ::: "memory");
        __syncthreads();
        if (c + 2 < NC) {
            load_chunk(sb + SM_TILES + ((c+2)%3)*STAGE_SZ, rows_s, tid,
                       g_xh, g_xl, Bh, Bl, n0, (c+2)*32, DIM);
            CP_COMMIT();
        }
        compute_chunk(sb + SM_TILES + (c%3)*STAGE_SZ, lane, mbase_w, nbase_w, acc);
    }

    // Epilogue: per-thread SwiGLU -> smem staging -> coalesced 16B stores
    __syncthreads();
    __nv_bfloat16* sh_h = (__nv_bfloat16*)(smem + SM_TILES);
    __nv_bfloat16* sh_l = sh_h + 128 * 72;
    #pragma unroll
    for (int mf = 0; mf < 2; mf++) {
        #pragma unroll
        for (int nf = 0; nf < 8; nf++) {
            const float* c = acc[mf][nf];
            int jloc = (nbase_w >> 1) + nf * 4 + (lane & 3);
            #pragma unroll
            for (int r2 = 0; r2 < 2; r2++) {
                int mrow = mbase_w + mf*16 + (lane >> 2) + r2*8;
                float a = c[r2*2 + 0], g = c[r2*2 + 1];
                float y = a * g / (1.f + __expf(-g));
                __nv_bfloat16 h = __float2bfloat16(y);
                __nv_bfloat16 l = __float2bfloat16(y - __bfloat162float(h));
                sh_h[mrow * 72 + jloc] = h;
                sh_l[mrow * 72 + jloc] = l;
            }
        }
    }
    __syncthreads();
    const int j0 = blockIdx.y * 64;
    #pragma unroll
    for (int i = 0; i < 4; i++) {
        int idx = tid + i * 256;
        int r = idx >> 3, cb = idx & 7;
        if (m0 + r < cnt) {
            size_t o = (size_t)rows_s[r] * HID + j0 + cb * 8;
            *(uint4*)(g_uh + o) = *(const uint4*)(sh_h + r * 72 + cb * 8);
            *(uint4*)(g_ul + o) = *(const uint4*)(sh_l + r * 72 + cb * 8);
        }
    }
}

// ====================================================================
// Kernel 4: down GEMM + skip add + scatter, smem-staged epilogue
// ====================================================================
__global__ __launch_bounds__(256, 2)
void down_mma_kernel(const float* __restrict__ x, float* __restrict__ out) {
    extern __shared__ char smem[];
    int* rows_s = (int*)smem;
    const uint32_t sb = smem_u32(smem);
    const int tid = threadIdx.x, lane = tid & 31, wid = tid >> 5;
    const int e = blockIdx.z;
    const int cnt = g_count[e];
    const int m0 = blockIdx.x * 128;
    if (m0 >= cnt) return;
    const int n0 = blockIdx.y * 128;

    if (tid < 128) {
        int i = m0 + tid;
        rows_s[tid] = g_tokmap[e * NTOK + (i < cnt ? i : cnt - 1)];
    }
    __syncthreads();

    const __nv_bfloat16* Bh = g_dwh + (size_t)e * 1024 * 2048;
    const __nv_bfloat16* Bl = g_dwl + (size_t)e * 1024 * 2048;

    const int NC = 64;   // 2048 / 32
    load_chunk(sb + SM_TILES,            rows_s, tid, g_uh, g_ul, Bh, Bl, n0, 0,  HID); CP_COMMIT();
    load_chunk(sb + SM_TILES + STAGE_SZ, rows_s, tid, g_uh, g_ul, Bh, Bl, n0, 32, HID); CP_COMMIT();

    float acc[2][8][4];
    #pragma unroll
    for (int a = 0; a < 2; a++)
        #pragma unroll
        for (int b = 0; b < 8; b++)
            #pragma unroll
            for (int c = 0; c < 4; c++) acc[a][b][c] = 0.f;

    const int mbase_w = (wid & 3) * 32, nbase_w = (wid >> 2) * 64;

    #pragma unroll 1
    for (int c = 0; c < NC; c++) {
        if (c < NC - 1) asm volatile("cp.async.wait_group 1;" ::: "memory");
        else            asm volatile("cp.async.wait_group 0;" ::: "memory");
        __syncthreads();
        if (c + 2 < NC) {
            load_chunk(sb + SM_TILES + ((c+2)%3)*STAGE_SZ, rows_s, tid,
                       g_uh, g_ul, Bh, Bl, n0, (c+2)*32, HID);
            CP_COMMIT();
        }
        compute_chunk(sb + SM_TILES + (c%3)*STAGE_SZ, lane, mbase_w, nbase_w, acc);
    }

    // Epilogue: stage fp32 results in smem, then coalesced skip-add + store
    __syncthreads();
    float* buf = (float*)(smem + SM_TILES);   // [128][132]
    #pragma unroll
    for (int mf = 0; mf < 2; mf++) {
        #pragma unroll
        for (int nf = 0; nf < 8; nf++) {
            const float* c = acc[mf][nf];
            int nloc = nbase_w + nf*8 + (lane & 3)*2;
            #pragma unroll
            for (int r2 = 0; r2 < 2; r2++) {
                int mrow = mbase_w + mf*16 + (lane >> 2) + r2*8;
                buf[mrow * 132 + nloc]     = c[r2*2 + 0];
                buf[mrow * 132 + nloc + 1] = c[r2*2 + 1];
            }
        }
    }
    __syncthreads();
    #pragma unroll
    for (int i = 0; i < 16; i++) {
        int idx = tid + i * 256;
        int r = idx >> 5, cb = idx & 31;
        if (m0 + r < cnt) {
            int token = rows_s[r];
            float4 v = *(const float4*)(buf + r * 132 + cb * 4);
            float4 s = *(const float4*)(x + (size_t)token * DIM + n0 + cb * 4);
            v.x += s.x; v.y += s.y; v.z += s.z; v.w += s.w;
            *(float4*)(out + (size_t)token * DIM + n0 + cb * 4) = v;
        }
    }
}

// ====================================================================
extern "C" void kernel_launch(void* const* d_in, const int* in_sizes, int n_in,
                              void* d_out, int out_size) {
    const float* x      = (const float*)d_in[0];   // [4,2048,1024]
    const float* scale  = (const float*)d_in[1];   // [1024]
    const float* cent   = (const float*)d_in[2];   // [8,1024]
    const float* up_w   = (const float*)d_in[3];   // [8,1024,4096]
    const float* down_w = (const float*)d_in[4];   // [8,2048,1024]
    float* out = (float*)d_out;                    // [4,2048,1024]

    cudaFuncSetAttribute(up_mma_kernel,   cudaFuncAttributeMaxDynamicSharedMemorySize, SMEM_MMA);
    cudaFuncSetAttribute(down_mma_kernel, cudaFuncAttributeMaxDynamicSharedMemorySize, SMEM_MMA);

    zero_counts_kernel<<<1, 32>>>();
    route_kernel<<<NTOK, 256>>>(x, scale, cent);
    conv_up_kernel<<<dim3(128, 16, NEXP), 256>>>(up_w);
    conv_down_kernel<<<dim3(32, 32, NEXP), 256>>>(down_w);
    up_mma_kernel<<<dim3(64, 32, NEXP), 256, SMEM_MMA>>>();
    down_mma_kernel<<<dim3(64, 8, NEXP), 256, SMEM_MMA>>>(x, out);
}